// round 9
// baseline (speedup 1.0000x reference)
#include <cuda_runtime.h>
#include <cuda_bf16.h>
#include <cstdint>

#define NN 100000
#define NE 1600000
#define NG 512
#define DIN 128
#define DHID 256
#define DOUT 128
#define NB ((NN + 255) / 256)   // 391 scan blocks

// ---------------- scratch (device globals; allocation-free rule) -----------
__device__ __nv_bfloat16 g_aggH[NN * DIN], g_aggL[NN * DIN];   // 25.6 MB x2

// CSR scratch
__device__ int g_deg [NN];
__device__ int g_excl[NN];
__device__ int g_off [NN];
__device__ int g_cur [NN];
__device__ int g_bsum[512];
__device__ int g_adj [NE];

// bf16 hi/lo weight planes, layout B[n][k]  (K-major = mma ".col" operand)
__device__ __nv_bfloat16 g_B1h[DHID * DIN ], g_B1l[DHID * DIN ];
__device__ __nv_bfloat16 g_B2h[DHID * DHID], g_B2l[DHID * DHID];
__device__ __nv_bfloat16 g_Boh[DOUT * DHID], g_Bol[DOUT * DHID];

// ---------------- helpers ---------------------------------------------------
__device__ __forceinline__ uint32_t smem_u32(const void* p) {
    uint32_t a;
    asm("{ .reg .u64 t; cvta.to.shared.u64 t, %1; cvt.u32.u64 %0, t; }" : "=r"(a) : "l"(p));
    return a;
}
__device__ __forceinline__ void red_add_v2(float* p, float a, float b) {
    asm volatile("red.global.add.v2.f32 [%0], {%1,%2};"
                 :: "l"(p), "f"(a), "f"(b) : "memory");
}
__device__ __forceinline__ void cpa16(uint32_t dst, const void* src, int sz) {
    asm volatile("cp.async.ca.shared.global [%0], [%1], 16, %2;"
                 :: "r"(dst), "l"(src), "r"(sz) : "memory");
}
#define CP_COMMIT()  asm volatile("cp.async.commit_group;" ::: "memory")
#define CP_WAIT(n)   asm volatile("cp.async.wait_group %0;" :: "n"(n) : "memory")

#define LDSM4(r, a) \
    asm volatile("ldmatrix.sync.aligned.m8n8.x4.shared.b16 {%0,%1,%2,%3}, [%4];" \
        : "=r"((r)[0]), "=r"((r)[1]), "=r"((r)[2]), "=r"((r)[3]) : "r"(a))

__device__ __forceinline__ void mma_bf16(float* d, const uint32_t* a, const uint32_t* b) {
    asm volatile("mma.sync.aligned.m16n8k16.row.col.f32.bf16.bf16.f32 "
        "{%0,%1,%2,%3}, {%4,%5,%6,%7}, {%8,%9}, {%0,%1,%2,%3};"
        : "+f"(d[0]), "+f"(d[1]), "+f"(d[2]), "+f"(d[3])
        : "r"(a[0]), "r"(a[1]), "r"(a[2]), "r"(a[3]), "r"(b[0]), "r"(b[1]));
}

__device__ __forceinline__ uint32_t pack_hi(float a, float b) {
    __nv_bfloat162 p = __halves2bfloat162(__float2bfloat16(a), __float2bfloat16(b));
    return *reinterpret_cast<uint32_t*>(&p);
}
__device__ __forceinline__ uint32_t pack_lo(float a, float b) {
    __nv_bfloat16 ha = __float2bfloat16(a), hb = __float2bfloat16(b);
    __nv_bfloat162 p = __halves2bfloat162(
        __float2bfloat16(a - __bfloat162float(ha)),
        __float2bfloat16(b - __bfloat162float(hb)));
    return *reinterpret_cast<uint32_t*>(&p);
}

// ---------------- CSR build -------------------------------------------------
__global__ void hist_kernel(const int* __restrict__ ei) {
    int e = blockIdx.x * blockDim.x + threadIdx.x;
    if (e < NE) atomicAdd(&g_deg[ei[NE + e]], 1);
}

__global__ void scan1_kernel() {
    __shared__ int s[256];
    int i = blockIdx.x * 256 + threadIdx.x;
    int v = (i < NN) ? g_deg[i] : 0;
    s[threadIdx.x] = v;
    __syncthreads();
    #pragma unroll
    for (int d = 1; d < 256; d <<= 1) {
        int t = (threadIdx.x >= d) ? s[threadIdx.x - d] : 0;
        __syncthreads();
        s[threadIdx.x] += t;
        __syncthreads();
    }
    if (i < NN) g_excl[i] = s[threadIdx.x] - v;
    if (threadIdx.x == 255) g_bsum[blockIdx.x] = s[255];
}

__global__ void scan2_kernel() {
    __shared__ int s[512];
    int i = threadIdx.x;
    int v = (i < NB) ? g_bsum[i] : 0;
    s[i] = v;
    __syncthreads();
    #pragma unroll
    for (int d = 1; d < 512; d <<= 1) {
        int t = (i >= d) ? s[i - d] : 0;
        __syncthreads();
        s[i] += t;
        __syncthreads();
    }
    if (i < NB) g_bsum[i] = s[i] - v;   // exclusive
}

__global__ void scan3_kernel() {
    int i = blockIdx.x * 256 + threadIdx.x;
    if (i < NN) {
        int o = g_excl[i] + g_bsum[blockIdx.x];
        g_off[i] = o;
        g_cur[i] = o;
    }
}

__global__ void fill_kernel(const int* __restrict__ ei) {
    int e = blockIdx.x * blockDim.x + threadIdx.x;
    if (e >= NE) return;
    int dst = ei[NE + e];
    int pos = atomicAdd(&g_cur[dst], 1);
    g_adj[pos] = ei[e];
}

// ---------------- gather: agg[n] = x[n] + sum_{s in adj[n]} x[s] ------------
__global__ void __launch_bounds__(256)
gather_kernel(const float4* __restrict__ x4) {
    int n = (blockIdx.x * blockDim.x + threadIdx.x) >> 5;
    int lane = threadIdx.x & 31;
    if (n >= NN) return;
    float4 acc = __ldg(&x4[(size_t)n * 32 + lane]);
    int beg = g_off[n], deg = g_deg[n], end = beg + deg;
    int i = beg;
    for (; i + 4 <= end; i += 4) {
        int s0 = g_adj[i], s1 = g_adj[i+1], s2 = g_adj[i+2], s3 = g_adj[i+3];
        float4 v0 = __ldg(&x4[(size_t)s0 * 32 + lane]);
        float4 v1 = __ldg(&x4[(size_t)s1 * 32 + lane]);
        float4 v2 = __ldg(&x4[(size_t)s2 * 32 + lane]);
        float4 v3 = __ldg(&x4[(size_t)s3 * 32 + lane]);
        acc.x += v0.x + v1.x + v2.x + v3.x;
        acc.y += v0.y + v1.y + v2.y + v3.y;
        acc.z += v0.z + v1.z + v2.z + v3.z;
        acc.w += v0.w + v1.w + v2.w + v3.w;
    }
    for (; i < end; i++) {
        int s = g_adj[i];
        float4 v = __ldg(&x4[(size_t)s * 32 + lane]);
        acc.x += v.x; acc.y += v.y; acc.z += v.z; acc.w += v.w;
    }
    uint2 h = make_uint2(pack_hi(acc.x, acc.y), pack_hi(acc.z, acc.w));
    uint2 l = make_uint2(pack_lo(acc.x, acc.y), pack_lo(acc.z, acc.w));
    *reinterpret_cast<uint2*>(g_aggH + (size_t)n * DIN + lane * 4) = h;
    *reinterpret_cast<uint2*>(g_aggL + (size_t)n * DIN + lane * 4) = l;
}

// ---------------- weight prep: W[K][N] -> Bh/Bl [N][K] bf16 ----------------
__global__ void prep_w_kernel(const float* __restrict__ W,
                              __nv_bfloat16* __restrict__ Bh,
                              __nv_bfloat16* __restrict__ Bl, int K, int N) {
    int idx = blockIdx.x * blockDim.x + threadIdx.x;
    if (idx >= K * N) return;
    int k = idx / N, n = idx % N;
    float v = W[idx];
    __nv_bfloat16 h = __float2bfloat16(v);
    __nv_bfloat16 l = __float2bfloat16(v - __bfloat162float(h));
    Bh[(size_t)n * K + k] = h;
    Bl[(size_t)n * K + k] = l;
}

// ---------------- fully fused MLP: one CTA per 128-row node block ----------
// Phase 1: h1 = relu(agg@W1+b1) -> smem (bf16 hi/lo, 128x256, pitch 528)
// Phase 2: per 32-col chunk: h2c = relu(h1@W2+b2) -> smem; accO += h2c@Wo
// Epilogue: pooled segment-sum of (accO + bo) via red.v2
__global__ void __launch_bounds__(256)
fused_mlp(const __nv_bfloat16* __restrict__ Ah_g,
          const __nv_bfloat16* __restrict__ Al_g,
          const __nv_bfloat16* __restrict__ W1h, const __nv_bfloat16* __restrict__ W1l,
          const __nv_bfloat16* __restrict__ W2h, const __nv_bfloat16* __restrict__ W2l,
          const __nv_bfloat16* __restrict__ Woh, const __nv_bfloat16* __restrict__ Wol,
          const float* __restrict__ b1, const float* __restrict__ b2,
          const float* __restrict__ bo,
          float* __restrict__ out, const int* __restrict__ batch_ids, int M)
{
    // smem map (bytes)
    constexpr int H1H = 0;            // 128 rows x 528 B
    constexpr int H1L = 67584;
    constexpr int STG = 135168;
    constexpr int W2S0 = STG;              // each stage: hi 32x144, lo +4608
    constexpr int H2B  = STG + 18432;      // hi 128x80, lo +10240
    constexpr int WOB  = STG + 38912;      // hi 128x80, lo +10240

    extern __shared__ __align__(16) char smem[];
    const uint32_t sb = smem_u32(smem);

    const int tid  = threadIdx.x;
    const int wid  = tid >> 5, lane = tid & 31;
    const int wm   = wid & 3, wn = wid >> 2;
    const int g    = lane >> 2, tig = lane & 3;
    const int row0 = blockIdx.x * 128;

    // ldmatrix lane patterns
    const int ar = (lane & 7) + ((lane >> 3) & 1) * 8;
    const int ak = ((lane >> 4) & 1) * 16;
    const int br = (lane & 7) + ((lane >> 4) & 1) * 8;
    const int bk = ((lane >> 3) & 1) * 16;

    // cp.async staging roles (phase1): thread -> rows (t>>2), (t>>2)+64; seg t&3
    const int rlo = tid >> 2, seg = tid & 3;

    auto issueP1 = [&](int s, int kc, int nh) {
        const int kof = kc * 32 + seg * 8;
        const uint32_t abase = sb + STG + s * 20480;
        const uint32_t bbase = sb + STG + 40960 + s * 20480;
        #pragma unroll
        for (int half = 0; half < 2; half++) {
            int row = half * 64 + rlo;
            int gr = row0 + row;
            int sz = (gr < M) ? 16 : 0;
            int grc = (gr < M) ? gr : 0;
            uint32_t doff = (uint32_t)(row * 80 + seg * 16);
            cpa16(abase + doff,         Ah_g + (size_t)grc * DIN + kof, sz);
            cpa16(abase + 10240 + doff, Al_g + (size_t)grc * DIN + kof, sz);
            int bn = nh * 128 + row;
            cpa16(bbase + doff,         W1h + (size_t)bn * DIN + kof, 16);
            cpa16(bbase + 10240 + doff, W1l + (size_t)bn * DIN + kof, 16);
        }
        CP_COMMIT();
    };

    // =========================== PHASE 1 ===========================
    for (int nh = 0; nh < 2; nh++) {
        float acc[2][8][4];
        #pragma unroll
        for (int mi = 0; mi < 2; mi++)
            #pragma unroll
            for (int ni = 0; ni < 8; ni++)
                #pragma unroll
                for (int q = 0; q < 4; q++) acc[mi][ni][q] = 0.f;

        issueP1(0, 0, nh);
        for (int kc = 0; kc < 4; kc++) {
            if (kc < 3) { issueP1((kc + 1) & 1, kc + 1, nh); CP_WAIT(1); }
            else        { CP_WAIT(0); }
            __syncthreads();
            const uint32_t soa = sb + STG + (kc & 1) * 20480;
            const uint32_t sob = sb + STG + 40960 + (kc & 1) * 20480;
            #pragma unroll
            for (int kk = 0; kk < 2; kk++) {
                uint32_t ah[2][4], al[2][4];
                #pragma unroll
                for (int mi = 0; mi < 2; mi++) {
                    uint32_t ao = soa + (uint32_t)((wm*32 + mi*16 + ar) * 80 + ak + kk*32);
                    LDSM4(ah[mi], ao);
                    LDSM4(al[mi], ao + 10240);
                }
                #pragma unroll
                for (int ni2 = 0; ni2 < 4; ni2++) {
                    uint32_t bo_ = sob + (uint32_t)((wn*64 + ni2*16 + br) * 80 + bk + kk*32);
                    uint32_t bh[4], bl[4];
                    LDSM4(bh, bo_);
                    LDSM4(bl, bo_ + 10240);
                    #pragma unroll
                    for (int mi = 0; mi < 2; mi++) {
                        mma_bf16(acc[mi][2*ni2],   ah[mi], bh);
                        mma_bf16(acc[mi][2*ni2],   ah[mi], bl);
                        mma_bf16(acc[mi][2*ni2],   al[mi], bh);
                        mma_bf16(acc[mi][2*ni2+1], ah[mi], bh + 2);
                        mma_bf16(acc[mi][2*ni2+1], ah[mi], bl + 2);
                        mma_bf16(acc[mi][2*ni2+1], al[mi], bh + 2);
                    }
                }
            }
            __syncthreads();
        }
        // epilogue: relu + bias -> H1 smem (hi/lo, pitch 528)
        #pragma unroll
        for (int mi = 0; mi < 2; mi++) {
            int rloc = wm * 32 + mi * 16 + g;
            #pragma unroll
            for (int ni = 0; ni < 8; ni++) {
                int c = nh * 128 + wn * 64 + ni * 8 + tig * 2;
                float bx = b1[c], by = b1[c + 1];
                float ox = fmaxf(acc[mi][ni][0] + bx, 0.f);
                float oy = fmaxf(acc[mi][ni][1] + by, 0.f);
                *reinterpret_cast<uint32_t*>(smem + H1H + rloc * 528 + c * 2) = pack_hi(ox, oy);
                *reinterpret_cast<uint32_t*>(smem + H1L + rloc * 528 + c * 2) = pack_lo(ox, oy);
                ox = fmaxf(acc[mi][ni][2] + bx, 0.f);
                oy = fmaxf(acc[mi][ni][3] + by, 0.f);
                *reinterpret_cast<uint32_t*>(smem + H1H + (rloc+8) * 528 + c * 2) = pack_hi(ox, oy);
                *reinterpret_cast<uint32_t*>(smem + H1L + (rloc+8) * 528 + c * 2) = pack_lo(ox, oy);
            }
        }
    }
    __syncthreads();

    // =========================== PHASE 2 ===========================
    float accO[2][8][4];
    #pragma unroll
    for (int mi = 0; mi < 2; mi++)
        #pragma unroll
        for (int ni = 0; ni < 8; ni++)
            #pragma unroll
            for (int q = 0; q < 4; q++) accO[mi][ni][q] = 0.f;

    // Wo tile: 128 n-rows x 32 k, pitch 80 -> 64B data per row (4 x 16B segs)
    auto issueWo = [&](int nc) {
        int pl = tid & 1, row = tid >> 1;
        const __nv_bfloat16* src = pl ? Wol : Woh;
        uint32_t dst = sb + WOB + pl * 10240 + row * 80;
        #pragma unroll
        for (int j = 0; j < 4; j++)
            cpa16(dst + j * 16, src + (size_t)row * DHID + nc * 32 + j * 8, 16);
        CP_COMMIT();
    };
    // W2 tile: 32 n-rows x 64 k, pitch 144 -> 128B data per row (8 x 16B segs)
    // 4 threads per (row, plane): each copies segs sg and sg+4
    auto issueW2 = [&](int s, int nc, int kc) {
        int pl = tid >> 7, rem = tid & 127;
        int row = rem >> 2, sg = rem & 3;
        const __nv_bfloat16* src = pl ? W2l : W2h;
        uint32_t dst = sb + W2S0 + s * 9216 + pl * 4608 + row * 144 + sg * 16;
        const __nv_bfloat16* sr = src + (size_t)(nc * 32 + row) * DHID + kc * 64 + sg * 8;
        cpa16(dst,      sr,      16);
        cpa16(dst + 64, sr + 32, 16);
        CP_COMMIT();
    };

    for (int nc = 0; nc < 8; nc++) {
        __syncthreads();   // previous nc's GEMM3 readers done; buffers free
        issueWo(nc);
        issueW2(0, nc, 0);

        float acc2[2][2][4];
        #pragma unroll
        for (int mi = 0; mi < 2; mi++)
            #pragma unroll
            for (int n8 = 0; n8 < 2; n8++)
                #pragma unroll
                for (int q = 0; q < 4; q++) acc2[mi][n8][q] = 0.f;

        for (int kc = 0; kc < 4; kc++) {
            if (kc < 3) { issueW2((kc + 1) & 1, nc, kc + 1); CP_WAIT(1); }
            else        { CP_WAIT(0); }
            __syncthreads();
            const uint32_t sow = sb + W2S0 + (kc & 1) * 9216;
            #pragma unroll
            for (int kk = 0; kk < 4; kk++) {
                uint32_t ah[2][4], al[2][4];
                #pragma unroll
                for (int mi = 0; mi < 2; mi++) {
                    uint32_t ao = sb + H1H + (uint32_t)((wm*32 + mi*16 + ar) * 528
                                     + kc * 128 + kk * 32 + ak);
                    LDSM4(ah[mi], ao);
                    LDSM4(al[mi], ao + (H1L - H1H));
                }
                uint32_t bo_ = sow + (uint32_t)((wn*16 + br) * 144 + kk * 32 + bk);
                uint32_t bh[4], bl[4];
                LDSM4(bh, bo_);
                LDSM4(bl, bo_ + 4608);
                #pragma unroll
                for (int mi = 0; mi < 2; mi++) {
                    mma_bf16(acc2[mi][0], ah[mi], bh);
                    mma_bf16(acc2[mi][0], ah[mi], bl);
                    mma_bf16(acc2[mi][0], al[mi], bh);
                    mma_bf16(acc2[mi][1], ah[mi], bh + 2);
                    mma_bf16(acc2[mi][1], ah[mi], bl + 2);
                    mma_bf16(acc2[mi][1], al[mi], bh + 2);
                }
            }
            __syncthreads();
        }
        // h2 chunk epilogue: bias2 + relu -> H2B (hi/lo, pitch 80)
        #pragma unroll
        for (int mi = 0; mi < 2; mi++) {
            int rloc = wm * 32 + mi * 16 + g;
            #pragma unroll
            for (int n8 = 0; n8 < 2; n8++) {
                int c = wn * 16 + n8 * 8 + tig * 2;
                float bx = b2[nc * 32 + c], by = b2[nc * 32 + c + 1];
                float ox = fmaxf(acc2[mi][n8][0] + bx, 0.f);
                float oy = fmaxf(acc2[mi][n8][1] + by, 0.f);
                *reinterpret_cast<uint32_t*>(smem + H2B + rloc * 80 + c * 2) = pack_hi(ox, oy);
                *reinterpret_cast<uint32_t*>(smem + H2B + 10240 + rloc * 80 + c * 2) = pack_lo(ox, oy);
                ox = fmaxf(acc2[mi][n8][2] + bx, 0.f);
                oy = fmaxf(acc2[mi][n8][3] + by, 0.f);
                *reinterpret_cast<uint32_t*>(smem + H2B + (rloc+8) * 80 + c * 2) = pack_hi(ox, oy);
                *reinterpret_cast<uint32_t*>(smem + H2B + 10240 + (rloc+8) * 80 + c * 2) = pack_lo(ox, oy);
            }
        }
        __syncthreads();   // h2 visible (Wo already complete via CP_WAIT(0)+sync)

        // GEMM3: accO += h2c @ Wo[:, nc*32:+32]
        #pragma unroll
        for (int kk = 0; kk < 2; kk++) {
            uint32_t ah[2][4], al[2][4];
            #pragma unroll
            for (int mi = 0; mi < 2; mi++) {
                uint32_t ao = sb + H2B + (uint32_t)((wm*32 + mi*16 + ar) * 80 + kk*32 + ak);
                LDSM4(ah[mi], ao);
                LDSM4(al[mi], ao + 10240);
            }
            #pragma unroll
            for (int ni2 = 0; ni2 < 4; ni2++) {
                uint32_t bo_ = sb + WOB + (uint32_t)((wn*64 + ni2*16 + br) * 80 + kk*32 + bk);
                uint32_t bh[4], bl[4];
                LDSM4(bh, bo_);
                LDSM4(bl, bo_ + 10240);
                #pragma unroll
                for (int mi = 0; mi < 2; mi++) {
                    mma_bf16(accO[mi][2*ni2],   ah[mi], bh);
                    mma_bf16(accO[mi][2*ni2],   ah[mi], bl);
                    mma_bf16(accO[mi][2*ni2],   al[mi], bh);
                    mma_bf16(accO[mi][2*ni2+1], ah[mi], bh + 2);
                    mma_bf16(accO[mi][2*ni2+1], ah[mi], bl + 2);
                    mma_bf16(accO[mi][2*ni2+1], al[mi], bh + 2);
                }
            }
        }
    }

    // ================== pooled epilogue (segment sum) ==================
    {
        int base = row0 + wm * 32 + g;
        int rows[4] = { base, base + 8, base + 16, base + 24 };
        int bids[4];
        #pragma unroll
        for (int e = 0; e < 4; e++)
            bids[e] = (rows[e] < M) ? batch_ids[rows[e]] : -1;

        #pragma unroll
        for (int ni = 0; ni < 8; ni++) {
            int cg = wn * 64 + ni * 8 + tig * 2;
            float bx = bo[cg], by = bo[cg + 1];
            float v0[4], v1[4];
            v0[0] = accO[0][ni][0] + bx; v1[0] = accO[0][ni][1] + by;
            v0[1] = accO[0][ni][2] + bx; v1[1] = accO[0][ni][3] + by;
            v0[2] = accO[1][ni][0] + bx; v1[2] = accO[1][ni][1] + by;
            v0[3] = accO[1][ni][2] + bx; v1[3] = accO[1][ni][3] + by;
            int cur = -1; float s0 = 0.f, s1 = 0.f;
            #pragma unroll
            for (int e = 0; e < 4; e++) {
                if (bids[e] < 0) continue;
                if (bids[e] != cur) {
                    if (cur >= 0) red_add_v2(&out[(size_t)cur * DOUT + cg], s0, s1);
                    cur = bids[e]; s0 = 0.f; s1 = 0.f;
                }
                s0 += v0[e]; s1 += v1[e];
            }
            if (cur >= 0) red_add_v2(&out[(size_t)cur * DOUT + cg], s0, s1);
        }
    }
}

// ---------------- launch ---------------------------------------------------
extern "C" void kernel_launch(void* const* d_in, const int* in_sizes, int n_in,
                              void* d_out, int out_size)
{
    const float* x   = (const float*)d_in[0];
    const int*   ei  = (const int*)d_in[1];
    const int*   bid = (const int*)d_in[2];
    const float* W1  = (const float*)d_in[3];
    const float* b1  = (const float*)d_in[4];
    const float* W2  = (const float*)d_in[5];
    const float* b2  = (const float*)d_in[6];
    const float* Wo  = (const float*)d_in[7];
    const float* bo  = (const float*)d_in[8];
    float*       out = (float*)d_out;

    __nv_bfloat16 *aggH, *aggL;
    cudaGetSymbolAddress((void**)&aggH, g_aggH);
    cudaGetSymbolAddress((void**)&aggL, g_aggL);
    __nv_bfloat16 *B1h, *B1l, *B2h, *B2l, *Boh, *Bol;
    cudaGetSymbolAddress((void**)&B1h, g_B1h); cudaGetSymbolAddress((void**)&B1l, g_B1l);
    cudaGetSymbolAddress((void**)&B2h, g_B2h); cudaGetSymbolAddress((void**)&B2l, g_B2l);
    cudaGetSymbolAddress((void**)&Boh, g_Boh); cudaGetSymbolAddress((void**)&Bol, g_Bol);
    int* deg; cudaGetSymbolAddress((void**)&deg, g_deg);

    constexpr int SMEM_TOT = 135168 + 81920;   // 217088
    cudaFuncSetAttribute(fused_mlp,
                         cudaFuncAttributeMaxDynamicSharedMemorySize, SMEM_TOT);

    // weight prep (bf16 hi/lo planes, [N][K])
    prep_w_kernel<<<(DIN  * DHID + 255) / 256, 256>>>(W1, B1h, B1l, DIN,  DHID);
    prep_w_kernel<<<(DHID * DHID + 255) / 256, 256>>>(W2, B2h, B2l, DHID, DHID);
    prep_w_kernel<<<(DHID * DOUT + 255) / 256, 256>>>(Wo, Boh, Bol, DHID, DOUT);

    // ---- CSR build ----
    cudaMemsetAsync(deg, 0, NN * sizeof(int));
    hist_kernel<<<(NE + 255) / 256, 256>>>(ei);
    scan1_kernel<<<NB, 256>>>();
    scan2_kernel<<<1, 512>>>();
    scan3_kernel<<<NB, 256>>>();
    fill_kernel<<<(NE + 255) / 256, 256>>>(ei);

    // ---- gather: agg = x + neighbor sum -> bf16 hi/lo ----
    gather_kernel<<<(NN * 32 + 255) / 256, 256>>>((const float4*)x);

    // ---- fused MLP + pool ----
    cudaMemsetAsync(d_out, 0, (size_t)out_size * sizeof(float));
    const int gx = (NN + 127) / 128;   // 782
    fused_mlp<<<gx, 256, SMEM_TOT>>>(aggH, aggL, B1h, B1l, B2h, B2l, Boh, Bol,
                                     b1, b2, bo, out, bid, NN);
}